// round 1
// baseline (speedup 1.0000x reference)
#include <cuda_runtime.h>

// Fast Walsh-Hadamard Transform, one row (N=4096 fp32) per CTA.
// 12 butterfly stages = 3 register rounds of 4 stages each, with
// skewed shared-memory exchanges between rounds.
//
// out[r] = FWHT(X[r]) * 2^{-6}   (normalized Hadamard)

#define HN      4096
#define NTHREADS 256
#define RPT      16          // registers (elements) per thread
// skew: smem address for logical element n is  n + (n >> 4)
#define SMEM_FLOATS (HN + (HN >> 4))   // 4352 floats = 17408 B

__global__ __launch_bounds__(NTHREADS, 4)
void fwht_kernel(const float* __restrict__ X, float* __restrict__ Y)
{
    __shared__ float s[SMEM_FLOATS];

    const int row = blockIdx.x;
    const float* __restrict__ x = X + (size_t)row * HN;
    float* __restrict__ y = Y + (size_t)row * HN;
    const int t = threadIdx.x;

    float v[RPT];

    // ---- Round 1: thread t owns n = t*16 + i  (bits 0..3 in registers) ----
    {
        const float4* xv = reinterpret_cast<const float4*>(x + t * RPT);
        float4 a0 = xv[0], a1 = xv[1], a2 = xv[2], a3 = xv[3];
        v[0]=a0.x; v[1]=a0.y; v[2]=a0.z; v[3]=a0.w;
        v[4]=a1.x; v[5]=a1.y; v[6]=a1.z; v[7]=a1.w;
        v[8]=a2.x; v[9]=a2.y; v[10]=a2.z; v[11]=a2.w;
        v[12]=a3.x; v[13]=a3.y; v[14]=a3.z; v[15]=a3.w;
    }

    // 4 butterfly stages fully in registers (strides 1,2,4,8 over i)
    #pragma unroll
    for (int st = 1; st < RPT; st <<= 1) {
        #pragma unroll
        for (int i = 0; i < RPT; i++) {
            if (!(i & st)) {
                float a = v[i], b = v[i ^ st];
                v[i]      = a + b;
                v[i ^ st] = a - b;
            }
        }
    }

    // write round-1 layout:  n = t*16+i  ->  addr = t*17 + i  (conflict-free)
    {
        const int wb = t * 17;
        #pragma unroll
        for (int i = 0; i < RPT; i++) s[wb + i] = v[i];
    }
    __syncthreads();

    // ---- Round 2: thread t owns n = (t>>4)*256 + i*16 + (t&15)  (bits 4..7) ----
    const int hi = t >> 4, lo = t & 15;
    const int rb2 = hi * 272 + lo;   // addr = hi*272 + i*17 + lo  (conflict-free)
    #pragma unroll
    for (int i = 0; i < RPT; i++) v[i] = s[rb2 + i * 17];

    #pragma unroll
    for (int st = 1; st < RPT; st <<= 1) {
        #pragma unroll
        for (int i = 0; i < RPT; i++) {
            if (!(i & st)) {
                float a = v[i], b = v[i ^ st];
                v[i]      = a + b;
                v[i ^ st] = a - b;
            }
        }
    }

    // write back to the SAME addresses (each addr owned by exactly one thread,
    // and we only overwrite what we ourselves read -> no sync needed before)
    #pragma unroll
    for (int i = 0; i < RPT; i++) s[rb2 + i * 17] = v[i];
    __syncthreads();

    // ---- Round 3: thread t owns n = i*256 + t  (bits 8..11) ----
    const int rb3 = t + (t >> 4);    // addr = i*272 + t + (t>>4)
    #pragma unroll
    for (int i = 0; i < RPT; i++) v[i] = s[i * 272 + rb3];

    #pragma unroll
    for (int st = 1; st < RPT; st <<= 1) {
        #pragma unroll
        for (int i = 0; i < RPT; i++) {
            if (!(i & st)) {
                float a = v[i], b = v[i ^ st];
                v[i]      = a + b;
                v[i ^ st] = a - b;
            }
        }
    }

    // scale by 2^{-6} (normalized Hadamard, N=4096) and store.
    // n = i*256 + t : per-i stores are 32 consecutive lanes -> coalesced 128B.
    #pragma unroll
    for (int i = 0; i < RPT; i++) {
        y[i * 256 + t] = v[i] * 0.015625f;
    }
}

extern "C" void kernel_launch(void* const* d_in, const int* in_sizes, int n_in,
                              void* d_out, int out_size)
{
    const float* X = (const float*)d_in[0];   // [8192, 4096] fp32
    // d_in[1] is the dense Hadamard matrix H -- not needed (FWHT).
    float* Y = (float*)d_out;

    const int rows = in_sizes[0] / HN;        // 8192
    fwht_kernel<<<rows, NTHREADS>>>(X, Y);
}